// round 3
// baseline (speedup 1.0000x reference)
#include <cuda_runtime.h>
#include <cuda_bf16.h>

// RNNModel: h_t = tanh(x_t @ W_ih^T + b_ih + h_{t-1} @ W_hh^T + b_hh), out = h_T @ fc_W^T + fc_b
// B=4096, T=512, D_IN=8, H=50, D_OUT=1
//
// Strategy: compute-bound fp32 recurrence -> use packed f32x2 FMA (FFMA2).
// Team of 25 threads per batch element. Thread u owns hidden units (2u, 2u+1),
// keeps its two W_hh rows PACKED in registers (50 x 64-bit), reads h from
// shared memory stored duplicated (h_k, h_k) so one LDS.128 feeds two f32x2 FMAs.
// One __syncthreads per timestep with double-buffered h.

#define B_SZ   4096
#define T_SZ   512
#define DIN    8
#define H_SZ   50
#define TEAM   25
#define NB     16                  // batches per block
#define NTHR   (TEAM * NB)         // 400 threads

typedef unsigned long long ull;

__device__ __forceinline__ ull pack2(float lo, float hi) {
    ull r;
    asm("mov.b64 %0, {%1, %2};" : "=l"(r) : "f"(lo), "f"(hi));
    return r;
}
__device__ __forceinline__ void unpack2(ull v, float& lo, float& hi) {
    asm("mov.b64 {%0, %1}, %2;" : "=f"(lo), "=f"(hi) : "l"(v));
}
__device__ __forceinline__ ull fma2(ull a, ull b, ull c) {
    ull r;
    asm("fma.rn.f32x2 %0, %1, %2, %3;" : "=l"(r) : "l"(a), "l"(b), "l"(c));
    return r;
}
__device__ __forceinline__ ull add2(ull a, ull b) {
    ull r;
    asm("add.rn.f32x2 %0, %1, %2;" : "=l"(r) : "l"(a), "l"(b));
    return r;
}

__device__ __forceinline__ float tanh_fast(float v) {
    // tanh(v) = 1 - 2/(exp(2v)+1); robust at extremes (exp->inf => 1, exp->0 => -1)
    float e = __expf(2.0f * v);
    return 1.0f - __fdividef(2.0f, e + 1.0f);
}

__global__ void __launch_bounds__(NTHR, 1)
rnn_kernel(const float* __restrict__ x,
           const float* __restrict__ Wih,
           const float* __restrict__ Whh,
           const float* __restrict__ bih,
           const float* __restrict__ bhh,
           const float* __restrict__ fcW,
           const float* __restrict__ fcb,
           float* __restrict__ out)
{
    // h stored duplicated: sh[buf][local_batch][k] = (h_k, h_k). 2*16*50*8 = 12.8 KB
    __shared__ ull sh[2][NB][H_SZ];

    const int tid = threadIdx.x;
    const int lb  = tid / TEAM;          // local batch 0..15
    const int u   = tid % TEAM;          // 0..24
    const int b   = blockIdx.x * NB + lb; // grid chosen so b < B_SZ always
    const int j0  = 2 * u;
    const int j1  = 2 * u + 1;

    // --- Preload this thread's two W_hh rows, packed (one-time) ---
    ull W2[H_SZ];
#pragma unroll
    for (int k = 0; k < H_SZ; k++)
        W2[k] = pack2(Whh[j0 * H_SZ + k], Whh[j1 * H_SZ + k]);

    ull Wi2[DIN];
#pragma unroll
    for (int d = 0; d < DIN; d++)
        Wi2[d] = pack2(Wih[j0 * DIN + d], Wih[j1 * DIN + d]);

    const ull bias2 = pack2(bih[j0] + bhh[j0], bih[j1] + bhh[j1]);

    // h0 = 0
    sh[0][lb][j0] = 0ull;
    sh[0][lb][j1] = 0ull;
    __syncthreads();

    // x row pointer for this batch (float4 granularity; 8 floats/row = 2 x float4)
    const float4* xp = (const float4*)(x + (size_t)b * T_SZ * DIN);
    float4 xa = xp[0];
    float4 xb = xp[1];

    int cur = 0;
#pragma unroll 1
    for (int t = 0; t < T_SZ; t++) {
        // prefetch next step's x (clamped; redundant load on last iter is harmless)
        const int tn = (t + 1 < T_SZ) ? (t + 1) : (T_SZ - 1);
        float4 nxa = xp[2 * tn];
        float4 nxb = xp[2 * tn + 1];

        // input projection + bias, split across two accumulator chains
        ull acc_a = bias2;
        ull acc_b = pack2(0.0f, 0.0f);
        acc_a = fma2(pack2(xa.x, xa.x), Wi2[0], acc_a);
        acc_b = fma2(pack2(xa.y, xa.y), Wi2[1], acc_b);
        acc_a = fma2(pack2(xa.z, xa.z), Wi2[2], acc_a);
        acc_b = fma2(pack2(xa.w, xa.w), Wi2[3], acc_b);
        acc_a = fma2(pack2(xb.x, xb.x), Wi2[4], acc_a);
        acc_b = fma2(pack2(xb.y, xb.y), Wi2[5], acc_b);
        acc_a = fma2(pack2(xb.z, xb.z), Wi2[6], acc_a);
        acc_b = fma2(pack2(xb.w, xb.w), Wi2[7], acc_b);

        // recurrence: acc += h_{t-1}[k] * W_hh[j][k]; h read duplicated from shared
        const ulonglong2* hrow = (const ulonglong2*)sh[cur][lb];
#pragma unroll
        for (int k2 = 0; k2 < H_SZ / 2; k2++) {
            ulonglong2 hh = hrow[k2];     // LDS.128: (h_k,h_k) and (h_{k+1},h_{k+1})
            acc_a = fma2(hh.x, W2[2 * k2],     acc_a);
            acc_b = fma2(hh.y, W2[2 * k2 + 1], acc_b);
        }

        ull s = add2(acc_a, acc_b);
        float p0, p1;
        unpack2(s, p0, p1);
        float v0 = tanh_fast(p0);
        float v1 = tanh_fast(p1);

        const int nxt = cur ^ 1;
        ulonglong2 wv;
        wv.x = pack2(v0, v0);
        wv.y = pack2(v1, v1);
        ((ulonglong2*)sh[nxt][lb])[u] = wv;   // STS.128, 16B aligned

        __syncthreads();
        cur = nxt;
        xa = nxa;
        xb = nxb;
    }

    // fc readout on last hidden state: out[b] = sum_j h[j] * fcW[j] + fcb[0]
    if (u == 0) {
        const ull* hrow = sh[cur][lb];
        float acc = fcb[0];
#pragma unroll
        for (int j = 0; j < H_SZ; j++) {
            float lo, hi;
            unpack2(hrow[j], lo, hi);
            acc = fmaf(lo, fcW[j], acc);
        }
        out[b] = acc;
    }
}

extern "C" void kernel_launch(void* const* d_in, const int* in_sizes, int n_in,
                              void* d_out, int out_size)
{
    const float* x   = (const float*)d_in[0];
    const float* Wih = (const float*)d_in[1];
    const float* Whh = (const float*)d_in[2];
    const float* bih = (const float*)d_in[3];
    const float* bhh = (const float*)d_in[4];
    const float* fcW = (const float*)d_in[5];
    const float* fcb = (const float*)d_in[6];
    float* out = (float*)d_out;

    rnn_kernel<<<B_SZ / NB, NTHR>>>(x, Wih, Whh, bih, bhh, fcW, fcb, out);
}